// round 8
// baseline (speedup 1.0000x reference)
#include <cuda_runtime.h>
#include <cuda_bf16.h>
#include <cstdint>

// Embedding gather: out[token, :] = table[ids[token], :]
// ids: [32*8192] int32, table: [256,256] f32, out: [32*8192, 256] f32.
//
// R8 = R7 + proxy fence fix. Bypass the l1tex store path: each block
// gathers 32 tokens (32 KB) into smem (STS rides the smem crossbar), then
// one cp.async.bulk 32 KB smem->global (TMA path, no per-warp STG
// wavefronts). R7 failed (rel_err 2.6e-2) because the generic-proxy STS
// were not fenced against the async-proxy bulk read; fence.proxy.async
// after __syncthreads fixes the stale-smem reads.

static constexpr int TOKENS      = 32 * 8192;        // 262144
static constexpr int EMBED       = 256;
static constexpr int VEC_PER_ROW = EMBED / 4;        // 64 float4 per row
static constexpr int TOK_PER_BLK = 32;               // 32 KB output per block
static constexpr int V4_PER_BLK  = TOK_PER_BLK * VEC_PER_ROW;  // 2048 float4
static constexpr int THREADS     = 256;
static constexpr int ITEMS       = V4_PER_BLK / THREADS;       // 8

__global__ __launch_bounds__(THREADS)
void embed_gather_kernel(const int* __restrict__ ids,
                         const float4* __restrict__ table4,
                         float4* __restrict__ out4)
{
    __shared__ alignas(128) float4 sbuf[V4_PER_BLK];   // 32 KB staging

    const int       tid         = threadIdx.x;
    const int       base_tok    = blockIdx.x * TOK_PER_BLK;
    const long long blk_base_v4 = (long long)blockIdx.x * V4_PER_BLK;

    // Gather phase: 8 independent ldg chains per thread, lane-contiguous
    // float4 (4 L1 lines per warp instruction), results staged via STS.
    #pragma unroll
    for (int k = 0; k < ITEMS; k++) {
        const int li  = tid + k * THREADS;             // 0..2047
        const int t   = li >> 6;                       // token within block
        const int c   = li & 63;                       // float4 column
        const int row = __ldg(&ids[base_tok + t]);     // warp-uniform
        sbuf[li] = __ldg(&table4[row * VEC_PER_ROW + c]);
    }
    __syncthreads();

    // Bulk async store: one 32 KB smem->global TMA transfer per block.
    if (tid == 0) {
        // Make generic-proxy STS visible to the async proxy before the
        // bulk engine reads smem.
        asm volatile("fence.proxy.async.shared::cta;" ::: "memory");

        uint32_t saddr;
        asm("{ .reg .u64 t; cvta.to.shared.u64 t, %1; cvt.u32.u64 %0, t; }"
            : "=r"(saddr) : "l"(sbuf));
        asm volatile(
            "cp.async.bulk.global.shared::cta.bulk_group [%0], [%1], %2;"
            :: "l"(out4 + blk_base_v4), "r"(saddr), "r"(V4_PER_BLK * 16)
            : "memory");
        asm volatile("cp.async.bulk.commit_group;" ::: "memory");
        // Block must not exit (smem reuse) before the bulk read completes.
        asm volatile("cp.async.bulk.wait_group 0;" ::: "memory");
    }
}

extern "C" void kernel_launch(void* const* d_in, const int* in_sizes, int n_in,
                              void* d_out, int out_size)
{
    const int*   ids   = (const int*)d_in[0];    // [32, 8192] int32
    const float* table = (const float*)d_in[1];  // [256, 256] f32
    float*       out   = (float*)d_out;          // [32, 8192, 256] f32

    const int blocks = TOKENS / TOK_PER_BLK;     // 8192

    embed_gather_kernel<<<blocks, THREADS>>>(
        ids, (const float4*)table, (float4*)out);
}